// round 1
// baseline (speedup 1.0000x reference)
#include <cuda_runtime.h>
#include <cstdint>

// Problem constants (fixed by the dataset instance).
#define BB 512
#define LL 512
#define CC 256
#define C4 (CC / 4)           // 64 float4 per row
#define NTHREADS 256
#define LGROUPS 4             // 256 / 64

// Least-squares constants for t = 0..511 (exact in fp64, stored as fp32):
//   sum_t  = 511*512/2            = 130816
//   sum_t2 = 511*512*1023/6       = 44608256
//   denom  = sum_t2 - sum_t^2/n   = 11184768
#define SUM_T     130816.0f
#define K1        255.5f          /* sum_t / n */
#define INV_DENOM (1.0f / 11184768.0f)
#define INV_N     (1.0f / 512.0f)

__global__ __launch_bounds__(NTHREADS, 4)
void lr_forecast_kernel(const float* __restrict__ x,
                        float* __restrict__ out,
                        int t_out_len)
{
    const int b   = blockIdx.x;
    const int tid = threadIdx.x;
    const int c4  = tid & (C4 - 1);   // channel group (4 channels)
    const int lg  = tid >> 6;         // l-stride group 0..3

    // ---- Pass 1: accumulate sum_y, sum_ty over this thread's l-stripe ----
    const float4* xb = reinterpret_cast<const float4*>(
                           x + (size_t)b * LL * CC) + c4;

    float4 sy  = make_float4(0.f, 0.f, 0.f, 0.f);
    float4 sty = make_float4(0.f, 0.f, 0.f, 0.f);

    #pragma unroll 8
    for (int l = lg; l < LL; l += LGROUPS) {
        float4 v = __ldg(&xb[(size_t)l * C4]);
        float tf = (float)l;
        sy.x += v.x;  sy.y += v.y;  sy.z += v.z;  sy.w += v.w;
        sty.x = fmaf(tf, v.x, sty.x);
        sty.y = fmaf(tf, v.y, sty.y);
        sty.z = fmaf(tf, v.z, sty.z);
        sty.w = fmaf(tf, v.w, sty.w);
    }

    // ---- Reduce the 4 l-groups in shared memory ----
    __shared__ float4 s_sy [LGROUPS][C4];
    __shared__ float4 s_sty[LGROUPS][C4];
    __shared__ float4 s_slope[C4];
    __shared__ float4 s_icept[C4];

    s_sy [lg][c4] = sy;
    s_sty[lg][c4] = sty;
    __syncthreads();

    if (lg == 0) {
        float4 Sy  = s_sy [0][c4];
        float4 Sty = s_sty[0][c4];
        #pragma unroll
        for (int g = 1; g < LGROUPS; g++) {
            float4 a = s_sy [g][c4];
            float4 t2 = s_sty[g][c4];
            Sy.x += a.x;  Sy.y += a.y;  Sy.z += a.z;  Sy.w += a.w;
            Sty.x += t2.x; Sty.y += t2.y; Sty.z += t2.z; Sty.w += t2.w;
        }
        float4 sl, ic;
        sl.x = (Sty.x - K1 * Sy.x) * INV_DENOM;
        sl.y = (Sty.y - K1 * Sy.y) * INV_DENOM;
        sl.z = (Sty.z - K1 * Sy.z) * INV_DENOM;
        sl.w = (Sty.w - K1 * Sy.w) * INV_DENOM;
        ic.x = (Sy.x - sl.x * SUM_T) * INV_N;
        ic.y = (Sy.y - sl.y * SUM_T) * INV_N;
        ic.z = (Sy.z - sl.z * SUM_T) * INV_N;
        ic.w = (Sy.w - sl.w * SUM_T) * INV_N;
        s_slope[c4] = sl;
        s_icept[c4] = ic;
    }
    __syncthreads();

    // ---- Pass 2: write out[b, t, :] = slope * t + intercept ----
    const float4 sl = s_slope[c4];
    const float4 ic = s_icept[c4];

    float4* ob = reinterpret_cast<float4*>(
                     out + (size_t)b * t_out_len * CC) + c4;

    #pragma unroll 4
    for (int t = lg; t < t_out_len; t += LGROUPS) {
        float tf = (float)t;
        float4 o;
        o.x = fmaf(sl.x, tf, ic.x);
        o.y = fmaf(sl.y, tf, ic.y);
        o.z = fmaf(sl.z, tf, ic.z);
        o.w = fmaf(sl.w, tf, ic.w);
        ob[(size_t)t * C4] = o;
    }
}

extern "C" void kernel_launch(void* const* d_in, const int* in_sizes, int n_in,
                              void* d_out, int out_size)
{
    const float* x = (const float*)d_in[0];
    float* out = (float*)d_out;
    // out is [B, L + pred_len, C]; recover the time dimension from out_size.
    int t_out_len = out_size / (BB * CC);   // 608 for pred_len = 96

    lr_forecast_kernel<<<BB, NTHREADS>>>(x, out, t_out_len);
}